// round 11
// baseline (speedup 1.0000x reference)
#include <cuda_runtime.h>
#include <cuda_fp16.h>
#include <cstdint>

// ---------------- problem constants ----------------
#define C_TOT   2048
#define L_TOT   9
#define K_TOT   (C_TOT * L_TOT)     // 18432
#define NPIX    4096
#define O_TOT   256

// ---------------- GEMM tiling ----------------
#define N_TILE   64
#define M_TILE   128
#define K_CHUNK  128
#define NCHUNK   (K_TOT / K_CHUNK)  // 144 = 9 l * 16

// ---------------- device scratch ----------------
__device__ __half g_a[O_TOT * K_TOT];           // A fp16, [o][l*2048+c]  9.4MB
__device__ __half g_xt[NPIX * C_TOT];           // fp16 x-transpose [p][c] 16.8MB
__device__ __half g_ca[16 * K_TOT];             // conv A fp16 [j(pad16)][l*2048+c]
__device__ float g_sigma[L_TOT * NPIX];
__device__ float g_smax[L_TOT * NPIX];
__device__ float g_scale[L_TOT];
__device__ float g_shift[L_TOT];

// ---------------- helpers ----------------
__device__ __forceinline__ uint32_t smem_u32(const void* p) {
    uint32_t a;
    asm("{ .reg .u64 t; cvta.to.shared.u64 t, %1; cvt.u32.u64 %0, t; }" : "=r"(a) : "l"(p));
    return a;
}
__device__ __forceinline__ void ldsm4(uint32_t* r, uint32_t addr) {
    asm volatile("ldmatrix.sync.aligned.m8n8.x4.shared.b16 {%0,%1,%2,%3}, [%4];"
        : "=r"(r[0]), "=r"(r[1]), "=r"(r[2]), "=r"(r[3]) : "r"(addr));
}
__device__ __forceinline__ void ldsm2(uint32_t* r, uint32_t addr) {
    asm volatile("ldmatrix.sync.aligned.m8n8.x2.shared.b16 {%0,%1}, [%2];"
        : "=r"(r[0]), "=r"(r[1]) : "r"(addr));
}
__device__ __forceinline__ void mma16816(float* d, const uint32_t* a, const uint32_t* b) {
    asm volatile(
        "mma.sync.aligned.m16n8k16.row.col.f32.f16.f16.f32 "
        "{%0,%1,%2,%3}, {%4,%5,%6,%7}, {%8,%9}, {%0,%1,%2,%3};"
        : "+f"(d[0]), "+f"(d[1]), "+f"(d[2]), "+f"(d[3])
        : "r"(a[0]), "r"(a[1]), "r"(a[2]), "r"(a[3]), "r"(b[0]), "r"(b[1]));
}
#define CP_ASYNC16(dst, src) \
    asm volatile("cp.async.cg.shared.global [%0], [%1], 16;" \
        :: "r"((uint32_t)(dst)), "l"(src) : "memory")
#define CP_ASYNC16Z(dst, src, ssz) \
    asm volatile("cp.async.cg.shared.global [%0], [%1], 16, %2;" \
        :: "r"((uint32_t)(dst)), "l"(src), "r"(ssz) : "memory")
#define CP_COMMIT()  asm volatile("cp.async.commit_group;" ::: "memory")
#define CP_WAIT0()   asm volatile("cp.async.wait_group 0;" ::: "memory")

// ---------------- shared GEMM SMEM layout ----------------
#define ROW_B     272u                      // 128 fp16 = 256B + 16B pad
#define A_TILE_B  (128u * ROW_B)            // 34816
#define B_TILE_B  (64u * ROW_B)             // 17408
#define BUF_B     (A_TILE_B + B_TILE_B)     // 52224
#define OFF_S     (2u * BUF_B)
#define SMEM_GEMM (OFF_S + 9u * 64u * 4u)   // 106752

// conv_mma smem
#define CA_TILE_B (16u * ROW_B)             // 4352
#define CBUF_B    (CA_TILE_B + B_TILE_B)    // 21760
#define SMEM_CONV (2u * CBUF_B)             // 43520

// ================= A prep =================
__global__ __launch_bounds__(256) void prep_a(const float* __restrict__ w) {
    int t = blockIdx.x * 256 + threadIdx.x;     // O_TOT*C_TOT
    int o = t >> 11, c = t & 2047;
    const float* src = w + (size_t)o * K_TOT + c * 9;
#pragma unroll
    for (int l = 0; l < 9; l++)
        g_a[(size_t)o * K_TOT + l * C_TOT + c] = __float2half_rn(src[l]);
}

// ================= conv A prep: g_ca[j][l*2048+c] (j padded to 16) =================
__global__ __launch_bounds__(256) void prep_ca(const float* __restrict__ cw) {
    int i = blockIdx.x * 256 + threadIdx.x;     // 16*K_TOT
    if (i < 16 * K_TOT) {
        int j = i / K_TOT, r = i - j * K_TOT;
        int l = r >> 11, c = r & 2047;
        __half v = __ushort_as_half((unsigned short)0);
        if (j < 9) v = __float2half_rn(cw[(size_t)j * K_TOT + c * 9 + l]);
        g_ca[i] = v;
    }
}

// ================= x transpose: g_xt[p][c] = fp16(x[n,c,y,x]) =================
__global__ __launch_bounds__(256) void transpose_x(const float* __restrict__ x) {
    __shared__ float t[64][65];
    const int tid = threadIdx.x;
    const int p0 = blockIdx.x * 64;
    const int c0 = blockIdx.y * 64;
    const int pc = tid & 63;
    const int cr = tid >> 6;            // 0..3
    const int p = p0 + pc;
    const int n = p >> 10, hw = p & 1023;
    const float* xp = x + (((size_t)(n * C_TOT + c0)) << 10) + hw;
#pragma unroll
    for (int it = 0; it < 16; it++) {
        int c = cr + it * 4;
        t[c][pc] = xp[(size_t)c << 10];
    }
    __syncthreads();
#pragma unroll
    for (int it = 0; it < 16; it++) {
        int prow = cr + it * 4;
        g_xt[(size_t)(p0 + prow) * C_TOT + c0 + pc] = __float2half_rn(t[pc][prow]);
    }
}

// ================= conv as tensor-core GEMM =================
// sigma[j,p] = sum_{l,c} ca[j][l*2048+c] * xt[p+off_l][c]
// grid 64 CTAs x 64 px; 8 warps x m16n8; K_CHUNK=128, 2-stage cp.async
__global__ __launch_bounds__(256, 1) void conv_mma() {
    extern __shared__ char smem_raw[];
    const uint32_t base = smem_u32(smem_raw);

    const int tid  = threadIdx.x;
    const int lane = tid & 31;
    const int warp_n = tid >> 5;                // 0..7, each owns 8 px
    const int p0 = blockIdx.x * 64;

    // cp.async geometry
    const int aRowT = tid >> 4;                 // 0..15
    const int aC16  = tid & 15;
    const __half* ag = g_ca + (size_t)aRowT * K_TOT + aC16 * 8;
    const int bRowT = tid >> 2;                 // 0..63
    const int bC16  = tid & 3;
    const int pb = p0 + bRowT;
    const int yb = (pb & 1023) >> 5, xb = pb & 31;
    const __half* xt_row = g_xt + (size_t)pb * C_TOT + bC16 * 8;

    float acc[4] = {0.f, 0.f, 0.f, 0.f};

    auto CPA = [&](int kt, uint32_t buf) {
        uint32_t aB = base + buf * CBUF_B
                    + (uint32_t)aRowT * ROW_B + (uint32_t)aC16 * 16;
        CP_ASYNC16(aB, ag + (size_t)kt * K_CHUNK);
        int l  = kt >> 4;
        int dy = l / 3 - 1, dx = l - l / 3 * 3 - 1;
        bool v = ((unsigned)(yb + dy) < 32u) & ((unsigned)(xb + dx) < 32u);
        uint32_t ssz = v ? 16u : 0u;
        const __half* gb = v ? (xt_row + (ptrdiff_t)(dy * 32 + dx) * C_TOT) : g_xt;
        gb += (size_t)(kt & 15) * K_CHUNK;
        uint32_t bB = base + buf * CBUF_B + CA_TILE_B
                    + (uint32_t)bRowT * ROW_B + (uint32_t)bC16 * 16;
#pragma unroll
        for (int it = 0; it < 4; it++)
            CP_ASYNC16Z(bB + (uint32_t)it * 64u, gb + (size_t)it * 32, ssz);
        CP_COMMIT();
    };

    auto COMPUTE = [&](uint32_t buf) {
        uint32_t aB = base + buf * CBUF_B;
        uint32_t bB = aB + CA_TILE_B;
        const uint32_t aAddr0 = aB + (uint32_t)(lane & 15) * ROW_B
                              + (uint32_t)(((lane >> 4) & 1) * 16);
        const uint32_t bAddr0 = bB + (uint32_t)(warp_n * 8 + (lane & 7)) * ROW_B
                              + (uint32_t)(((lane >> 3) & 1) * 16);
#pragma unroll
        for (int ks = 0; ks < 8; ks++) {
            uint32_t aF[4], bF[2];
            ldsm4(aF, aAddr0 + ks * 32);
            ldsm2(bF, bAddr0 + ks * 32);
            mma16816(acc, aF, bF);
        }
    };

    CPA(0, 0);
    CP_WAIT0();
    __syncthreads();

    for (int kt = 0; kt < NCHUNK; kt++) {
        const uint32_t buf = kt & 1;
        if (kt + 1 < NCHUNK) CPA(kt + 1, buf ^ 1);
        COMPUTE(buf);
        CP_WAIT0();
        __syncthreads();
    }

    // epilogue: sigma[j][p]
    int j0 = lane >> 2;
    int p  = p0 + warp_n * 8 + (lane & 3) * 2;
    if (j0 < 9) {
        g_sigma[j0 * NPIX + p]     = acc[0];
        g_sigma[j0 * NPIX + p + 1] = acc[1];
    }
    if (j0 + 8 < 9) {       // only j0==0
        g_sigma[(j0 + 8) * NPIX + p]     = acc[2];
        g_sigma[(j0 + 8) * NPIX + p + 1] = acc[3];
    }
}

// ================= BN stats =================
__global__ __launch_bounds__(256) void bn_stats(const float* __restrict__ gamma,
                                                const float* __restrict__ beta) {
    __shared__ float shs[256], shq[256];
    const int j = blockIdx.x, tid = threadIdx.x;
    float s = 0.f, q = 0.f;
    for (int i = tid; i < NPIX; i += 256) {
        float v = g_sigma[j * NPIX + i];
        s += v; q += v * v;
    }
    shs[tid] = s; shq[tid] = q;
    __syncthreads();
    for (int st = 128; st > 0; st >>= 1) {
        if (tid < st) { shs[tid] += shs[tid + st]; shq[tid] += shq[tid + st]; }
        __syncthreads();
    }
    if (tid == 0) {
        float mean = shs[0] * (1.f / NPIX);
        float var  = shq[0] * (1.f / NPIX) - mean * mean;
        float inv  = rsqrtf(var + 1e-5f);
        float sc   = gamma[j] * inv;
        g_scale[j] = sc;
        g_shift[j] = beta[j] - mean * sc;
    }
}

__global__ __launch_bounds__(256) void softmax_k() {
    int p = blockIdx.x * 256 + threadIdx.x;
    float v[9];
    float m = -1e30f;
#pragma unroll
    for (int j = 0; j < 9; j++) {
        v[j] = g_sigma[j * NPIX + p] * g_scale[j] + g_shift[j];
        m = fmaxf(m, v[j]);
    }
    float s = 0.f;
#pragma unroll
    for (int j = 0; j < 9; j++) { v[j] = expf(v[j] - m); s += v[j]; }
    float inv = 1.f / s;
#pragma unroll
    for (int j = 0; j < 9; j++) g_smax[j * NPIX + p] = v[j] * inv;
}

// ================= main GEMM (2-stage, R9 config) =================
// out[o,p] = sum_l s_l[p] * sum_c A[o][l*2048+c] * xt[p + off_l][c]
__global__ __launch_bounds__(256, 1) void gemm_mma(float* __restrict__ out) {
    extern __shared__ char smem_raw[];
    const uint32_t base = smem_u32(smem_raw);
    float* s_sh = (float*)(smem_raw + OFF_S);

    const int tid  = threadIdx.x;
    const int lane = tid & 31;
    const int wid  = tid >> 5;
    const int warp_m = wid & 3;
    const int warp_n = wid >> 2;
    const int p0     = blockIdx.x * N_TILE;
    const int o_base = blockIdx.y * M_TILE;
    const int n_img  = p0 >> 10;

    for (int i = tid; i < 9 * N_TILE; i += 256) {
        int l = i >> 6, pp = i & 63;
        s_sh[i] = g_smax[l * NPIX + p0 + pp];
    }
    __syncthreads();

    const int aRowT = tid >> 4;
    const int aC16  = tid & 15;
    const __half* ag = g_a + (size_t)(o_base + aRowT) * K_TOT + aC16 * 8;
    const int bRowT = tid >> 2;
    const int bC16  = tid & 3;
    const int pb = p0 + bRowT;
    const int yb = (pb & 1023) >> 5, xb = pb & 31;
    const __half* xt_row = g_xt + (size_t)pb * C_TOT + bC16 * 8;

    const uint32_t aRow  = (uint32_t)(warp_m * 32 + (lane & 15));
    const uint32_t aColB = (uint32_t)(((lane >> 4) & 1) * 16);
    const uint32_t bRow  = (uint32_t)(warp_n * 32 + ((lane >> 4) & 1) * 8 + (lane & 7));
    const uint32_t bColB = (uint32_t)(((lane >> 3) & 1) * 16);

    float fin[2][4][4], cur[2][4][4];
#pragma unroll
    for (int a = 0; a < 2; a++)
#pragma unroll
        for (int b = 0; b < 4; b++)
#pragma unroll
            for (int c = 0; c < 4; c++) { fin[a][b][c] = 0.f; cur[a][b][c] = 0.f; }

    auto CPA = [&](int kt, uint32_t buf) {
        uint32_t aB = base + buf * BUF_B
                    + (uint32_t)aRowT * ROW_B + (uint32_t)aC16 * 16;
        const __half* ga = ag + (size_t)kt * K_CHUNK;
#pragma unroll
        for (int it = 0; it < 8; it++)
            CP_ASYNC16(aB + (uint32_t)it * 16u * ROW_B, ga + (size_t)it * 16 * K_TOT);
        int l  = kt >> 4;
        int dy = l / 3 - 1, dx = l - l / 3 * 3 - 1;
        bool v = ((unsigned)(yb + dy) < 32u) & ((unsigned)(xb + dx) < 32u);
        uint32_t ssz = v ? 16u : 0u;
        const __half* gb = v ? (xt_row + (ptrdiff_t)(dy * 32 + dx) * C_TOT) : g_xt;
        gb += (size_t)(kt & 15) * K_CHUNK;
        uint32_t bB = base + buf * BUF_B + A_TILE_B
                    + (uint32_t)bRowT * ROW_B + (uint32_t)bC16 * 16;
#pragma unroll
        for (int it = 0; it < 4; it++)
            CP_ASYNC16Z(bB + (uint32_t)it * 64u, gb + (size_t)it * 32, ssz);
        CP_COMMIT();
    };

    auto COMPUTE = [&](uint32_t buf) {
        uint32_t aB = base + buf * BUF_B;
        uint32_t bB = aB + A_TILE_B;
#pragma unroll
        for (int ks = 0; ks < 8; ks++) {
            uint32_t aF[2][4], bF[2][4];
#pragma unroll
            for (int ms = 0; ms < 2; ms++)
                ldsm4(aF[ms], aB + (aRow + ms * 16) * ROW_B + aColB + ks * 32);
#pragma unroll
            for (int np = 0; np < 2; np++)
                ldsm4(bF[np], bB + (bRow + np * 16) * ROW_B + bColB + ks * 32);
#pragma unroll
            for (int ms = 0; ms < 2; ms++)
#pragma unroll
                for (int ns = 0; ns < 4; ns++)
                    mma16816(cur[ms][ns], aF[ms], &bF[ns >> 1][(ns & 1) * 2]);
        }
    };

    CPA(0, 0);
    CP_WAIT0();
    __syncthreads();

    for (int lt = 0; lt < 9; lt++) {
#pragma unroll 1
        for (int ki = 0; ki < 16; ki++) {
            const int kt = lt * 16 + ki;
            const uint32_t buf = kt & 1;
            if (kt + 1 < NCHUNK) CPA(kt + 1, buf ^ 1);
            COMPUTE(buf);
            CP_WAIT0();
            __syncthreads();
        }
#pragma unroll
        for (int ns = 0; ns < 4; ns++) {
            int cn = warp_n * 32 + ns * 8 + (lane & 3) * 2;
            float s0 = s_sh[lt * 64 + cn];
            float s1 = s_sh[lt * 64 + cn + 1];
#pragma unroll
            for (int ms = 0; ms < 2; ms++) {
                fin[ms][ns][0] += cur[ms][ns][0] * s0;
                fin[ms][ns][1] += cur[ms][ns][1] * s1;
                fin[ms][ns][2] += cur[ms][ns][2] * s0;
                fin[ms][ns][3] += cur[ms][ns][3] * s1;
                cur[ms][ns][0] = 0.f; cur[ms][ns][1] = 0.f;
                cur[ms][ns][2] = 0.f; cur[ms][ns][3] = 0.f;
            }
        }
    }

    const int hw0 = (p0 & 1023);
#pragma unroll
    for (int ms = 0; ms < 2; ms++)
#pragma unroll
        for (int ns = 0; ns < 4; ns++) {
            int row  = o_base + warp_m * 32 + ms * 16 + (lane >> 2);
            int coln = hw0 + warp_n * 32 + ns * 8 + (lane & 3) * 2;
            float* p1 = out + (((size_t)(n_img * O_TOT + row)) << 10) + coln;
            *(float2*)p1 = make_float2(fin[ms][ns][0], fin[ms][ns][1]);
            float* p2 = p1 + ((size_t)8 << 10);
            *(float2*)p2 = make_float2(fin[ms][ns][2], fin[ms][ns][3]);
        }
}

// ---------------- launch ----------------
extern "C" void kernel_launch(void* const* d_in, const int* in_sizes, int n_in,
                              void* d_out, int out_size) {
    const float* x      = (const float*)d_in[0];
    const float* conv_w = (const float*)d_in[1];
    const float* gamma  = (const float*)d_in[2];
    const float* beta   = (const float*)d_in[3];
    const float* weight = (const float*)d_in[4];
    float* out = (float*)d_out;

    cudaFuncSetAttribute(gemm_mma, cudaFuncAttributeMaxDynamicSharedMemorySize, SMEM_GEMM);
    cudaFuncSetAttribute(conv_mma, cudaFuncAttributeMaxDynamicSharedMemorySize, SMEM_CONV);

    prep_a      <<<(O_TOT * C_TOT) / 256, 256>>>(weight);
    transpose_x <<<dim3(NPIX / 64, C_TOT / 64), 256>>>(x);
    prep_ca     <<<(16 * K_TOT + 255) / 256, 256>>>(conv_w);
    conv_mma    <<<NPIX / 64, 256, SMEM_CONV>>>();
    bn_stats    <<<9, 256>>>(gamma, beta);
    softmax_k   <<<NPIX / 256, 256>>>();
    gemm_mma    <<<dim3(NPIX / N_TILE, O_TOT / M_TILE), 256, SMEM_GEMM>>>(out);
}

// round 13
// speedup vs baseline: 1.1996x; 1.1996x over previous
#include <cuda_runtime.h>
#include <cuda_fp16.h>
#include <cstdint>

// ---------------- problem constants ----------------
#define C_TOT   2048
#define L_TOT   9
#define K_TOT   (C_TOT * L_TOT)     // 18432
#define NPIX    4096
#define O_TOT   256

// ---------------- GEMM tiling ----------------
#define N_TILE   64
#define M_TILE   128
#define K_CHUNK  128
#define NCHUNK   (K_TOT / K_CHUNK)  // 144 = 9 l * 16

// ---------------- device scratch ----------------
__device__ __half g_a[O_TOT * K_TOT];           // A fp16, [o][l*2048+c]  9.4MB
__device__ __half g_xt[NPIX * C_TOT];           // fp16 x-transpose [p][c] 16.8MB
__device__ __half g_ca[16 * K_TOT];             // conv A fp16 [j(pad16)][l*2048+c]
__device__ float g_cpart[L_TOT * L_TOT * NPIX]; // conv partials [l][j][p] 1.3MB
__device__ float g_sigma[L_TOT * NPIX];
__device__ float g_smax[L_TOT * NPIX];
__device__ float g_scale[L_TOT];
__device__ float g_shift[L_TOT];

// ---------------- helpers ----------------
__device__ __forceinline__ uint32_t smem_u32(const void* p) {
    uint32_t a;
    asm("{ .reg .u64 t; cvta.to.shared.u64 t, %1; cvt.u32.u64 %0, t; }" : "=r"(a) : "l"(p));
    return a;
}
__device__ __forceinline__ void ldsm4(uint32_t* r, uint32_t addr) {
    asm volatile("ldmatrix.sync.aligned.m8n8.x4.shared.b16 {%0,%1,%2,%3}, [%4];"
        : "=r"(r[0]), "=r"(r[1]), "=r"(r[2]), "=r"(r[3]) : "r"(addr));
}
__device__ __forceinline__ void ldsm2(uint32_t* r, uint32_t addr) {
    asm volatile("ldmatrix.sync.aligned.m8n8.x2.shared.b16 {%0,%1}, [%2];"
        : "=r"(r[0]), "=r"(r[1]) : "r"(addr));
}
__device__ __forceinline__ void mma16816(float* d, const uint32_t* a, const uint32_t* b) {
    asm volatile(
        "mma.sync.aligned.m16n8k16.row.col.f32.f16.f16.f32 "
        "{%0,%1,%2,%3}, {%4,%5,%6,%7}, {%8,%9}, {%0,%1,%2,%3};"
        : "+f"(d[0]), "+f"(d[1]), "+f"(d[2]), "+f"(d[3])
        : "r"(a[0]), "r"(a[1]), "r"(a[2]), "r"(a[3]), "r"(b[0]), "r"(b[1]));
}
#define CP_ASYNC16(dst, src) \
    asm volatile("cp.async.cg.shared.global [%0], [%1], 16;" \
        :: "r"((uint32_t)(dst)), "l"(src) : "memory")
#define CP_ASYNC16Z(dst, src, ssz) \
    asm volatile("cp.async.cg.shared.global [%0], [%1], 16, %2;" \
        :: "r"((uint32_t)(dst)), "l"(src), "r"(ssz) : "memory")
#define CP_COMMIT()  asm volatile("cp.async.commit_group;" ::: "memory")
#define CP_WAIT0()   asm volatile("cp.async.wait_group 0;" ::: "memory")

// ---------------- shared GEMM SMEM layout ----------------
#define ROW_B     272u                      // 128 fp16 = 256B + 16B pad
#define A_TILE_B  (128u * ROW_B)            // 34816
#define B_TILE_B  (64u * ROW_B)             // 17408
#define BUF_B     (A_TILE_B + B_TILE_B)     // 52224
#define OFF_S     (2u * BUF_B)
#define SMEM_GEMM (OFF_S + 9u * 64u * 4u)   // 106752

// conv_mma smem
#define CA_TILE_B (16u * ROW_B)             // 4352
#define CBUF_B    (CA_TILE_B + B_TILE_B)    // 21760
#define SMEM_CONV (2u * CBUF_B)             // 43520

// ================= A prep =================
__global__ __launch_bounds__(256) void prep_a(const float* __restrict__ w) {
    int t = blockIdx.x * 256 + threadIdx.x;     // O_TOT*C_TOT
    int o = t >> 11, c = t & 2047;
    const float* src = w + (size_t)o * K_TOT + c * 9;
#pragma unroll
    for (int l = 0; l < 9; l++)
        g_a[(size_t)o * K_TOT + l * C_TOT + c] = __float2half_rn(src[l]);
}

// ================= conv A prep: g_ca[j][l*2048+c] (j padded to 16) =================
__global__ __launch_bounds__(256) void prep_ca(const float* __restrict__ cw) {
    int i = blockIdx.x * 256 + threadIdx.x;     // 16*K_TOT
    if (i < 16 * K_TOT) {
        int j = i / K_TOT, r = i - j * K_TOT;
        int l = r >> 11, c = r & 2047;
        __half v = __ushort_as_half((unsigned short)0);
        if (j < 9) v = __float2half_rn(cw[(size_t)j * K_TOT + c * 9 + l]);
        g_ca[i] = v;
    }
}

// ================= x transpose: g_xt[p][c] = fp16(x[n,c,y,x]) =================
__global__ __launch_bounds__(256) void transpose_x(const float* __restrict__ x) {
    __shared__ float t[64][65];
    const int tid = threadIdx.x;
    const int p0 = blockIdx.x * 64;
    const int c0 = blockIdx.y * 64;
    const int pc = tid & 63;
    const int cr = tid >> 6;            // 0..3
    const int p = p0 + pc;
    const int n = p >> 10, hw = p & 1023;
    const float* xp = x + (((size_t)(n * C_TOT + c0)) << 10) + hw;
#pragma unroll
    for (int it = 0; it < 16; it++) {
        int c = cr + it * 4;
        t[c][pc] = xp[(size_t)c << 10];
    }
    __syncthreads();
#pragma unroll
    for (int it = 0; it < 16; it++) {
        int prow = cr + it * 4;
        g_xt[(size_t)(p0 + prow) * C_TOT + c0 + pc] = __float2half_rn(t[pc][prow]);
    }
}

// ================= conv as tensor-core GEMM, split over l =================
// cpart[l][j][p] = sum_c ca[j][l*2048+c] * xt[p+off_l][c]
// grid (64, 9); 8 warps x m16n8; K=2048 per CTA (16 chunks), 2-stage cp.async
__global__ __launch_bounds__(256, 1) void conv_mma() {
    extern __shared__ char smem_raw[];
    const uint32_t base = smem_u32(smem_raw);

    const int tid  = threadIdx.x;
    const int lane = tid & 31;
    const int warp_n = tid >> 5;                // 0..7, each owns 8 px
    const int p0 = blockIdx.x * 64;
    const int l  = blockIdx.y;
    const int dy = l / 3 - 1, dx = l % 3 - 1;

    // cp.async geometry
    const int aRowT = tid >> 4;                 // 0..15
    const int aC16  = tid & 15;
    const __half* ag = g_ca + (size_t)aRowT * K_TOT + (size_t)l * C_TOT + aC16 * 8;
    const int bRowT = tid >> 2;                 // 0..63
    const int bC16  = tid & 3;
    const int pb = p0 + bRowT;
    const int yb = (pb & 1023) >> 5, xb = pb & 31;
    const bool v = ((unsigned)(yb + dy) < 32u) & ((unsigned)(xb + dx) < 32u);
    const uint32_t ssz = v ? 16u : 0u;
    const __half* gb_base = v
        ? (g_xt + (size_t)pb * C_TOT + (ptrdiff_t)(dy * 32 + dx) * C_TOT + bC16 * 8)
        : g_xt;

    float acc[4] = {0.f, 0.f, 0.f, 0.f};

    auto CPA = [&](int ki, uint32_t buf) {
        uint32_t aB = base + buf * CBUF_B
                    + (uint32_t)aRowT * ROW_B + (uint32_t)aC16 * 16;
        CP_ASYNC16(aB, ag + (size_t)ki * K_CHUNK);
        const __half* gb = gb_base + (size_t)ki * K_CHUNK;
        uint32_t bB = base + buf * CBUF_B + CA_TILE_B
                    + (uint32_t)bRowT * ROW_B + (uint32_t)bC16 * 16;
#pragma unroll
        for (int it = 0; it < 4; it++)
            CP_ASYNC16Z(bB + (uint32_t)it * 64u, gb + (size_t)it * 32, ssz);
        CP_COMMIT();
    };

    auto COMPUTE = [&](uint32_t buf) {
        uint32_t aB = base + buf * CBUF_B;
        uint32_t bB = aB + CA_TILE_B;
        const uint32_t aAddr0 = aB + (uint32_t)(lane & 15) * ROW_B
                              + (uint32_t)(((lane >> 4) & 1) * 16);
        const uint32_t bAddr0 = bB + (uint32_t)(warp_n * 8 + (lane & 7)) * ROW_B
                              + (uint32_t)(((lane >> 3) & 1) * 16);
#pragma unroll
        for (int ks = 0; ks < 8; ks++) {
            uint32_t aF[4], bF[2];
            ldsm4(aF, aAddr0 + ks * 32);
            ldsm2(bF, bAddr0 + ks * 32);
            mma16816(acc, aF, bF);
        }
    };

    CPA(0, 0);
    CP_WAIT0();
    __syncthreads();

    for (int ki = 0; ki < 16; ki++) {
        const uint32_t buf = ki & 1;
        if (ki + 1 < 16) CPA(ki + 1, buf ^ 1);
        COMPUTE(buf);
        CP_WAIT0();
        __syncthreads();
    }

    // epilogue: cpart[l][j][p]
    int j0 = lane >> 2;
    int p  = p0 + warp_n * 8 + (lane & 3) * 2;
    float* cp = g_cpart + (size_t)l * (L_TOT * NPIX);
    if (j0 < 9) {
        cp[j0 * NPIX + p]     = acc[0];
        cp[j0 * NPIX + p + 1] = acc[1];
    }
    if (j0 == 0) {          // row j = 8
        cp[8 * NPIX + p]     = acc[2];
        cp[8 * NPIX + p + 1] = acc[3];
    }
}

// ================= conv reduce over l =================
__global__ __launch_bounds__(256) void conv_reduce() {
    int i = blockIdx.x * 256 + threadIdx.x;     // 9*4096
    if (i < L_TOT * NPIX) {
        float s = 0.f;
#pragma unroll
        for (int l = 0; l < L_TOT; l++)
            s += g_cpart[(size_t)l * (L_TOT * NPIX) + i];
        g_sigma[i] = s;
    }
}

// ================= BN stats =================
__global__ __launch_bounds__(256) void bn_stats(const float* __restrict__ gamma,
                                                const float* __restrict__ beta) {
    __shared__ float shs[256], shq[256];
    const int j = blockIdx.x, tid = threadIdx.x;
    float s = 0.f, q = 0.f;
    for (int i = tid; i < NPIX; i += 256) {
        float v = g_sigma[j * NPIX + i];
        s += v; q += v * v;
    }
    shs[tid] = s; shq[tid] = q;
    __syncthreads();
    for (int st = 128; st > 0; st >>= 1) {
        if (tid < st) { shs[tid] += shs[tid + st]; shq[tid] += shq[tid + st]; }
        __syncthreads();
    }
    if (tid == 0) {
        float mean = shs[0] * (1.f / NPIX);
        float var  = shq[0] * (1.f / NPIX) - mean * mean;
        float inv  = rsqrtf(var + 1e-5f);
        float sc   = gamma[j] * inv;
        g_scale[j] = sc;
        g_shift[j] = beta[j] - mean * sc;
    }
}

__global__ __launch_bounds__(256) void softmax_k() {
    int p = blockIdx.x * 256 + threadIdx.x;
    float v[9];
    float m = -1e30f;
#pragma unroll
    for (int j = 0; j < 9; j++) {
        v[j] = g_sigma[j * NPIX + p] * g_scale[j] + g_shift[j];
        m = fmaxf(m, v[j]);
    }
    float s = 0.f;
#pragma unroll
    for (int j = 0; j < 9; j++) { v[j] = expf(v[j] - m); s += v[j]; }
    float inv = 1.f / s;
#pragma unroll
    for (int j = 0; j < 9; j++) g_smax[j * NPIX + p] = v[j] * inv;
}

// ================= main GEMM (2-stage, R9 config) =================
// out[o,p] = sum_l s_l[p] * sum_c A[o][l*2048+c] * xt[p + off_l][c]
__global__ __launch_bounds__(256, 1) void gemm_mma(float* __restrict__ out) {
    extern __shared__ char smem_raw[];
    const uint32_t base = smem_u32(smem_raw);
    float* s_sh = (float*)(smem_raw + OFF_S);

    const int tid  = threadIdx.x;
    const int lane = tid & 31;
    const int wid  = tid >> 5;
    const int warp_m = wid & 3;
    const int warp_n = wid >> 2;
    const int p0     = blockIdx.x * N_TILE;
    const int o_base = blockIdx.y * M_TILE;
    const int n_img  = p0 >> 10;

    for (int i = tid; i < 9 * N_TILE; i += 256) {
        int l = i >> 6, pp = i & 63;
        s_sh[i] = g_smax[l * NPIX + p0 + pp];
    }
    __syncthreads();

    const int aRowT = tid >> 4;
    const int aC16  = tid & 15;
    const __half* ag = g_a + (size_t)(o_base + aRowT) * K_TOT + aC16 * 8;
    const int bRowT = tid >> 2;
    const int bC16  = tid & 3;
    const int pb = p0 + bRowT;
    const int yb = (pb & 1023) >> 5, xb = pb & 31;
    const __half* xt_row = g_xt + (size_t)pb * C_TOT + bC16 * 8;

    const uint32_t aRow  = (uint32_t)(warp_m * 32 + (lane & 15));
    const uint32_t aColB = (uint32_t)(((lane >> 4) & 1) * 16);
    const uint32_t bRow  = (uint32_t)(warp_n * 32 + ((lane >> 4) & 1) * 8 + (lane & 7));
    const uint32_t bColB = (uint32_t)(((lane >> 3) & 1) * 16);

    float fin[2][4][4], cur[2][4][4];
#pragma unroll
    for (int a = 0; a < 2; a++)
#pragma unroll
        for (int b = 0; b < 4; b++)
#pragma unroll
            for (int c = 0; c < 4; c++) { fin[a][b][c] = 0.f; cur[a][b][c] = 0.f; }

    auto CPA = [&](int kt, uint32_t buf) {
        uint32_t aB = base + buf * BUF_B
                    + (uint32_t)aRowT * ROW_B + (uint32_t)aC16 * 16;
        const __half* ga = ag + (size_t)kt * K_CHUNK;
#pragma unroll
        for (int it = 0; it < 8; it++)
            CP_ASYNC16(aB + (uint32_t)it * 16u * ROW_B, ga + (size_t)it * 16 * K_TOT);
        int l  = kt >> 4;
        int dy = l / 3 - 1, dx = l - l / 3 * 3 - 1;
        bool v = ((unsigned)(yb + dy) < 32u) & ((unsigned)(xb + dx) < 32u);
        uint32_t ssz = v ? 16u : 0u;
        const __half* gb = v ? (xt_row + (ptrdiff_t)(dy * 32 + dx) * C_TOT) : g_xt;
        gb += (size_t)(kt & 15) * K_CHUNK;
        uint32_t bB = base + buf * BUF_B + A_TILE_B
                    + (uint32_t)bRowT * ROW_B + (uint32_t)bC16 * 16;
#pragma unroll
        for (int it = 0; it < 4; it++)
            CP_ASYNC16Z(bB + (uint32_t)it * 64u, gb + (size_t)it * 32, ssz);
        CP_COMMIT();
    };

    auto COMPUTE = [&](uint32_t buf) {
        uint32_t aB = base + buf * BUF_B;
        uint32_t bB = aB + A_TILE_B;
#pragma unroll
        for (int ks = 0; ks < 8; ks++) {
            uint32_t aF[2][4], bF[2][4];
#pragma unroll
            for (int ms = 0; ms < 2; ms++)
                ldsm4(aF[ms], aB + (aRow + ms * 16) * ROW_B + aColB + ks * 32);
#pragma unroll
            for (int np = 0; np < 2; np++)
                ldsm4(bF[np], bB + (bRow + np * 16) * ROW_B + bColB + ks * 32);
#pragma unroll
            for (int ms = 0; ms < 2; ms++)
#pragma unroll
                for (int ns = 0; ns < 4; ns++)
                    mma16816(cur[ms][ns], aF[ms], &bF[ns >> 1][(ns & 1) * 2]);
        }
    };

    CPA(0, 0);
    CP_WAIT0();
    __syncthreads();

    for (int lt = 0; lt < 9; lt++) {
#pragma unroll 1
        for (int ki = 0; ki < 16; ki++) {
            const int kt = lt * 16 + ki;
            const uint32_t buf = kt & 1;
            if (kt + 1 < NCHUNK) CPA(kt + 1, buf ^ 1);
            COMPUTE(buf);
            CP_WAIT0();
            __syncthreads();
        }
#pragma unroll
        for (int ns = 0; ns < 4; ns++) {
            int cn = warp_n * 32 + ns * 8 + (lane & 3) * 2;
            float s0 = s_sh[lt * 64 + cn];
            float s1 = s_sh[lt * 64 + cn + 1];
#pragma unroll
            for (int ms = 0; ms < 2; ms++) {
                fin[ms][ns][0] += cur[ms][ns][0] * s0;
                fin[ms][ns][1] += cur[ms][ns][1] * s1;
                fin[ms][ns][2] += cur[ms][ns][2] * s0;
                fin[ms][ns][3] += cur[ms][ns][3] * s1;
                cur[ms][ns][0] = 0.f; cur[ms][ns][1] = 0.f;
                cur[ms][ns][2] = 0.f; cur[ms][ns][3] = 0.f;
            }
        }
    }

    const int hw0 = (p0 & 1023);
#pragma unroll
    for (int ms = 0; ms < 2; ms++)
#pragma unroll
        for (int ns = 0; ns < 4; ns++) {
            int row  = o_base + warp_m * 32 + ms * 16 + (lane >> 2);
            int coln = hw0 + warp_n * 32 + ns * 8 + (lane & 3) * 2;
            float* p1 = out + (((size_t)(n_img * O_TOT + row)) << 10) + coln;
            *(float2*)p1 = make_float2(fin[ms][ns][0], fin[ms][ns][1]);
            float* p2 = p1 + ((size_t)8 << 10);
            *(float2*)p2 = make_float2(fin[ms][ns][2], fin[ms][ns][3]);
        }
}

// ---------------- launch ----------------
extern "C" void kernel_launch(void* const* d_in, const int* in_sizes, int n_in,
                              void* d_out, int out_size) {
    const float* x      = (const float*)d_in[0];
    const float* conv_w = (const float*)d_in[1];
    const float* gamma  = (const float*)d_in[2];
    const float* beta   = (const float*)d_in[3];
    const float* weight = (const float*)d_in[4];
    float* out = (float*)d_out;

    cudaFuncSetAttribute(gemm_mma, cudaFuncAttributeMaxDynamicSharedMemorySize, SMEM_GEMM);
    cudaFuncSetAttribute(conv_mma, cudaFuncAttributeMaxDynamicSharedMemorySize, SMEM_CONV);

    prep_a      <<<(O_TOT * C_TOT) / 256, 256>>>(weight);
    transpose_x <<<dim3(NPIX / 64, C_TOT / 64), 256>>>(x);
    prep_ca     <<<(16 * K_TOT + 255) / 256, 256>>>(conv_w);
    conv_mma    <<<dim3(NPIX / 64, L_TOT), 256, SMEM_CONV>>>();
    conv_reduce <<<(L_TOT * NPIX + 255) / 256, 256>>>();
    bn_stats    <<<9, 256>>>(gamma, beta);
    softmax_k   <<<NPIX / 256, 256>>>();
    gemm_mma    <<<dim3(NPIX / N_TILE, O_TOT / M_TILE), 256, SMEM_GEMM>>>(out);
}

// round 14
// speedup vs baseline: 1.2096x; 1.0084x over previous
#include <cuda_runtime.h>
#include <cuda_fp16.h>
#include <cstdint>

// ---------------- problem constants ----------------
#define C_TOT   2048
#define L_TOT   9
#define K_TOT   (C_TOT * L_TOT)     // 18432
#define NPIX    4096
#define O_TOT   256

// ---------------- GEMM tiling ----------------
#define N_TILE   64
#define M_TILE   128
#define K_CHUNK  128
#define NCHUNK   (K_TOT / K_CHUNK)  // 144 = 9 l * 16

// ---------------- device scratch ----------------
__device__ __half g_a[O_TOT * K_TOT];           // A fp16, [o][l*2048+c]  9.4MB
__device__ __half g_xt[NPIX * C_TOT];           // fp16 x-transpose [p][c] 16.8MB
__device__ __half g_ca[16 * K_TOT];             // conv A fp16 [j(pad16)][l*2048+c]
__device__ float g_cpart[L_TOT * L_TOT * NPIX]; // conv partials [l][j][p] 1.3MB
__device__ float g_sigma[L_TOT * NPIX];
__device__ float g_scale[L_TOT];
__device__ float g_shift[L_TOT];

// ---------------- helpers ----------------
__device__ __forceinline__ uint32_t smem_u32(const void* p) {
    uint32_t a;
    asm("{ .reg .u64 t; cvta.to.shared.u64 t, %1; cvt.u32.u64 %0, t; }" : "=r"(a) : "l"(p));
    return a;
}
__device__ __forceinline__ void ldsm4(uint32_t* r, uint32_t addr) {
    asm volatile("ldmatrix.sync.aligned.m8n8.x4.shared.b16 {%0,%1,%2,%3}, [%4];"
        : "=r"(r[0]), "=r"(r[1]), "=r"(r[2]), "=r"(r[3]) : "r"(addr));
}
__device__ __forceinline__ void ldsm2(uint32_t* r, uint32_t addr) {
    asm volatile("ldmatrix.sync.aligned.m8n8.x2.shared.b16 {%0,%1}, [%2];"
        : "=r"(r[0]), "=r"(r[1]) : "r"(addr));
}
__device__ __forceinline__ void mma16816(float* d, const uint32_t* a, const uint32_t* b) {
    asm volatile(
        "mma.sync.aligned.m16n8k16.row.col.f32.f16.f16.f32 "
        "{%0,%1,%2,%3}, {%4,%5,%6,%7}, {%8,%9}, {%0,%1,%2,%3};"
        : "+f"(d[0]), "+f"(d[1]), "+f"(d[2]), "+f"(d[3])
        : "r"(a[0]), "r"(a[1]), "r"(a[2]), "r"(a[3]), "r"(b[0]), "r"(b[1]));
}
#define CP_ASYNC16(dst, src) \
    asm volatile("cp.async.cg.shared.global [%0], [%1], 16;" \
        :: "r"((uint32_t)(dst)), "l"(src) : "memory")
#define CP_ASYNC16Z(dst, src, ssz) \
    asm volatile("cp.async.cg.shared.global [%0], [%1], 16, %2;" \
        :: "r"((uint32_t)(dst)), "l"(src), "r"(ssz) : "memory")
#define CP_COMMIT()  asm volatile("cp.async.commit_group;" ::: "memory")
#define CP_WAIT0()   asm volatile("cp.async.wait_group 0;" ::: "memory")

// ---------------- shared GEMM SMEM layout ----------------
#define ROW_B     272u                      // 128 fp16 = 256B + 16B pad
#define A_TILE_B  (128u * ROW_B)            // 34816
#define B_TILE_B  (64u * ROW_B)             // 17408
#define BUF_B     (A_TILE_B + B_TILE_B)     // 52224
#define OFF_S     (2u * BUF_B)
#define SMEM_GEMM (OFF_S + 9u * 64u * 4u)   // 106752

// conv_mma smem
#define CA_TILE_B (16u * ROW_B)             // 4352
#define CBUF_B    (CA_TILE_B + B_TILE_B)    // 21760
#define SMEM_CONV (2u * CBUF_B)             // 43520

// grid split constants
#define TX_BLOCKS  ((NPIX / 64) * (C_TOT / 64))   // 2048
#define CA_BLOCKS  ((16 * K_TOT) / 256)           // 1152
#define CV_BLOCKS  ((NPIX / 64) * L_TOT)          // 576
#define PA_BLOCKS  ((O_TOT * C_TOT) / 256)        // 2048

// ================= fused pre: transpose_x + prep_ca =================
__global__ __launch_bounds__(256) void fused_pre(const float* __restrict__ x,
                                                 const float* __restrict__ cw) {
    const int bid = blockIdx.x;
    const int tid = threadIdx.x;
    if (bid < TX_BLOCKS) {
        // ---- transpose_x: g_xt[p][c] = fp16(x[n,c,y,x]) ----
        __shared__ float t[64][65];
        const int p0 = (bid & 63) * 64;
        const int c0 = (bid >> 6) * 64;
        const int pc = tid & 63;
        const int cr = tid >> 6;
        const int p = p0 + pc;
        const int n = p >> 10, hw = p & 1023;
        const float* xp = x + (((size_t)(n * C_TOT + c0)) << 10) + hw;
#pragma unroll
        for (int it = 0; it < 16; it++) {
            int c = cr + it * 4;
            t[c][pc] = xp[(size_t)c << 10];
        }
        __syncthreads();
#pragma unroll
        for (int it = 0; it < 16; it++) {
            int prow = cr + it * 4;
            g_xt[(size_t)(p0 + prow) * C_TOT + c0 + pc] = __float2half_rn(t[pc][prow]);
        }
    } else {
        // ---- prep_ca: g_ca[j][l*2048+c], j padded to 16 ----
        int i = (bid - TX_BLOCKS) * 256 + tid;
        int j = i / K_TOT, r = i - j * K_TOT;
        int l = r >> 11, c = r & 2047;
        __half v = __ushort_as_half((unsigned short)0);
        if (j < 9) v = __float2half_rn(cw[(size_t)j * K_TOT + c * 9 + l]);
        g_ca[i] = v;
    }
}

// ================= fused conv: conv_mma (first) + prep_a (filler) =================
// conv: cpart[l][j][p] = sum_c ca[j][l*2048+c] * xt[p+off_l][c]
__global__ __launch_bounds__(256, 1) void fused_conv(const float* __restrict__ w) {
    const int bid = blockIdx.x;
    const int tid = threadIdx.x;

    if (bid >= CV_BLOCKS) {
        // ---- prep_a: weight fp32 -> fp16, [o][l*2048+c] ----
        int t = (bid - CV_BLOCKS) * 256 + tid;
        int o = t >> 11, c = t & 2047;
        const float* src = w + (size_t)o * K_TOT + c * 9;
#pragma unroll
        for (int l = 0; l < 9; l++)
            g_a[(size_t)o * K_TOT + l * C_TOT + c] = __float2half_rn(src[l]);
        return;
    }

    extern __shared__ char smem_raw[];
    const uint32_t base = smem_u32(smem_raw);

    const int lane = tid & 31;
    const int warp_n = tid >> 5;
    const int p0 = (bid & 63) * 64;
    const int l  = bid >> 6;
    const int dy = l / 3 - 1, dx = l % 3 - 1;

    const int aRowT = tid >> 4;
    const int aC16  = tid & 15;
    const __half* ag = g_ca + (size_t)aRowT * K_TOT + (size_t)l * C_TOT + aC16 * 8;
    const int bRowT = tid >> 2;
    const int bC16  = tid & 3;
    const int pb = p0 + bRowT;
    const int yb = (pb & 1023) >> 5, xb = pb & 31;
    const bool v = ((unsigned)(yb + dy) < 32u) & ((unsigned)(xb + dx) < 32u);
    const uint32_t ssz = v ? 16u : 0u;
    const __half* gb_base = v
        ? (g_xt + (size_t)pb * C_TOT + (ptrdiff_t)(dy * 32 + dx) * C_TOT + bC16 * 8)
        : g_xt;

    float acc[4] = {0.f, 0.f, 0.f, 0.f};

    auto CPA = [&](int ki, uint32_t buf) {
        uint32_t aB = base + buf * CBUF_B
                    + (uint32_t)aRowT * ROW_B + (uint32_t)aC16 * 16;
        CP_ASYNC16(aB, ag + (size_t)ki * K_CHUNK);
        const __half* gb = gb_base + (size_t)ki * K_CHUNK;
        uint32_t bB = base + buf * CBUF_B + CA_TILE_B
                    + (uint32_t)bRowT * ROW_B + (uint32_t)bC16 * 16;
#pragma unroll
        for (int it = 0; it < 4; it++)
            CP_ASYNC16Z(bB + (uint32_t)it * 64u, gb + (size_t)it * 32, ssz);
        CP_COMMIT();
    };

    auto COMPUTE = [&](uint32_t buf) {
        uint32_t aB = base + buf * CBUF_B;
        uint32_t bB = aB + CA_TILE_B;
        const uint32_t aAddr0 = aB + (uint32_t)(lane & 15) * ROW_B
                              + (uint32_t)(((lane >> 4) & 1) * 16);
        const uint32_t bAddr0 = bB + (uint32_t)(warp_n * 8 + (lane & 7)) * ROW_B
                              + (uint32_t)(((lane >> 3) & 1) * 16);
#pragma unroll
        for (int ks = 0; ks < 8; ks++) {
            uint32_t aF[4], bF[2];
            ldsm4(aF, aAddr0 + ks * 32);
            ldsm2(bF, bAddr0 + ks * 32);
            mma16816(acc, aF, bF);
        }
    };

    CPA(0, 0);
    CP_WAIT0();
    __syncthreads();

    for (int ki = 0; ki < 16; ki++) {
        const uint32_t buf = ki & 1;
        if (ki + 1 < 16) CPA(ki + 1, buf ^ 1);
        COMPUTE(buf);
        CP_WAIT0();
        __syncthreads();
    }

    int j0 = lane >> 2;
    int p  = p0 + warp_n * 8 + (lane & 3) * 2;
    float* cp = g_cpart + (size_t)l * (L_TOT * NPIX);
    if (j0 < 9) {
        cp[j0 * NPIX + p]     = acc[0];
        cp[j0 * NPIX + p + 1] = acc[1];
    }
    if (j0 == 0) {
        cp[8 * NPIX + p]     = acc[2];
        cp[8 * NPIX + p + 1] = acc[3];
    }
}

// ================= fused reduce + BN stats (grid 9) =================
__global__ __launch_bounds__(256) void reduce_bn(const float* __restrict__ gamma,
                                                 const float* __restrict__ beta) {
    __shared__ float shs[256], shq[256];
    const int j = blockIdx.x, tid = threadIdx.x;
    float s = 0.f, q = 0.f;
    for (int i = tid; i < NPIX; i += 256) {
        float v = 0.f;
#pragma unroll
        for (int l = 0; l < L_TOT; l++)
            v += g_cpart[(size_t)l * (L_TOT * NPIX) + j * NPIX + i];
        g_sigma[j * NPIX + i] = v;
        s += v; q += v * v;
    }
    shs[tid] = s; shq[tid] = q;
    __syncthreads();
    for (int st = 128; st > 0; st >>= 1) {
        if (tid < st) { shs[tid] += shs[tid + st]; shq[tid] += shq[tid + st]; }
        __syncthreads();
    }
    if (tid == 0) {
        float mean = shs[0] * (1.f / NPIX);
        float var  = shq[0] * (1.f / NPIX) - mean * mean;
        float inv  = rsqrtf(var + 1e-5f);
        float sc   = gamma[j] * inv;
        g_scale[j] = sc;
        g_shift[j] = beta[j] - mean * sc;
    }
}

// ================= main GEMM (softmax folded into prologue) =================
// out[o,p] = sum_l s_l[p] * sum_c A[o][l*2048+c] * xt[p + off_l][c]
__global__ __launch_bounds__(256, 1) void gemm_mma(float* __restrict__ out) {
    extern __shared__ char smem_raw[];
    const uint32_t base = smem_u32(smem_raw);
    float* s_sh = (float*)(smem_raw + OFF_S);

    const int tid  = threadIdx.x;
    const int lane = tid & 31;
    const int wid  = tid >> 5;
    const int warp_m = wid & 3;
    const int warp_n = wid >> 2;
    const int p0     = blockIdx.x * N_TILE;
    const int o_base = blockIdx.y * M_TILE;
    const int n_img  = p0 >> 10;

    // inline softmax for this pixel tile
    if (tid < 64) {
        const int pp = tid;
        float v[9];
        float m = -1e30f;
#pragma unroll
        for (int j = 0; j < 9; j++) {
            v[j] = g_sigma[j * NPIX + p0 + pp] * g_scale[j] + g_shift[j];
            m = fmaxf(m, v[j]);
        }
        float sum = 0.f;
#pragma unroll
        for (int j = 0; j < 9; j++) { v[j] = expf(v[j] - m); sum += v[j]; }
        float inv = 1.f / sum;
#pragma unroll
        for (int j = 0; j < 9; j++) s_sh[j * 64 + pp] = v[j] * inv;
    }
    __syncthreads();

    const int aRowT = tid >> 4;
    const int aC16  = tid & 15;
    const __half* ag = g_a + (size_t)(o_base + aRowT) * K_TOT + aC16 * 8;
    const int bRowT = tid >> 2;
    const int bC16  = tid & 3;
    const int pb = p0 + bRowT;
    const int yb = (pb & 1023) >> 5, xb = pb & 31;
    const __half* xt_row = g_xt + (size_t)pb * C_TOT + bC16 * 8;

    const uint32_t aRow  = (uint32_t)(warp_m * 32 + (lane & 15));
    const uint32_t aColB = (uint32_t)(((lane >> 4) & 1) * 16);
    const uint32_t bRow  = (uint32_t)(warp_n * 32 + ((lane >> 4) & 1) * 8 + (lane & 7));
    const uint32_t bColB = (uint32_t)(((lane >> 3) & 1) * 16);

    float fin[2][4][4], cur[2][4][4];
#pragma unroll
    for (int a = 0; a < 2; a++)
#pragma unroll
        for (int b = 0; b < 4; b++)
#pragma unroll
            for (int c = 0; c < 4; c++) { fin[a][b][c] = 0.f; cur[a][b][c] = 0.f; }

    auto CPA = [&](int kt, uint32_t buf) {
        uint32_t aB = base + buf * BUF_B
                    + (uint32_t)aRowT * ROW_B + (uint32_t)aC16 * 16;
        const __half* ga = ag + (size_t)kt * K_CHUNK;
#pragma unroll
        for (int it = 0; it < 8; it++)
            CP_ASYNC16(aB + (uint32_t)it * 16u * ROW_B, ga + (size_t)it * 16 * K_TOT);
        int l  = kt >> 4;
        int dy = l / 3 - 1, dx = l - l / 3 * 3 - 1;
        bool v = ((unsigned)(yb + dy) < 32u) & ((unsigned)(xb + dx) < 32u);
        uint32_t ssz = v ? 16u : 0u;
        const __half* gb = v ? (xt_row + (ptrdiff_t)(dy * 32 + dx) * C_TOT) : g_xt;
        gb += (size_t)(kt & 15) * K_CHUNK;
        uint32_t bB = base + buf * BUF_B + A_TILE_B
                    + (uint32_t)bRowT * ROW_B + (uint32_t)bC16 * 16;
#pragma unroll
        for (int it = 0; it < 4; it++)
            CP_ASYNC16Z(bB + (uint32_t)it * 64u, gb + (size_t)it * 32, ssz);
        CP_COMMIT();
    };

    auto COMPUTE = [&](uint32_t buf) {
        uint32_t aB = base + buf * BUF_B;
        uint32_t bB = aB + A_TILE_B;
#pragma unroll
        for (int ks = 0; ks < 8; ks++) {
            uint32_t aF[2][4], bF[2][4];
#pragma unroll
            for (int ms = 0; ms < 2; ms++)
                ldsm4(aF[ms], aB + (aRow + ms * 16) * ROW_B + aColB + ks * 32);
#pragma unroll
            for (int np = 0; np < 2; np++)
                ldsm4(bF[np], bB + (bRow + np * 16) * ROW_B + bColB + ks * 32);
#pragma unroll
            for (int ms = 0; ms < 2; ms++)
#pragma unroll
                for (int ns = 0; ns < 4; ns++)
                    mma16816(cur[ms][ns], aF[ms], &bF[ns >> 1][(ns & 1) * 2]);
        }
    };

    CPA(0, 0);
    CP_WAIT0();
    __syncthreads();

    for (int lt = 0; lt < 9; lt++) {
#pragma unroll 1
        for (int ki = 0; ki < 16; ki++) {
            const int kt = lt * 16 + ki;
            const uint32_t buf = kt & 1;
            if (kt + 1 < NCHUNK) CPA(kt + 1, buf ^ 1);
            COMPUTE(buf);
            CP_WAIT0();
            __syncthreads();
        }
#pragma unroll
        for (int ns = 0; ns < 4; ns++) {
            int cn = warp_n * 32 + ns * 8 + (lane & 3) * 2;
            float s0 = s_sh[lt * 64 + cn];
            float s1 = s_sh[lt * 64 + cn + 1];
#pragma unroll
            for (int ms = 0; ms < 2; ms++) {
                fin[ms][ns][0] += cur[ms][ns][0] * s0;
                fin[ms][ns][1] += cur[ms][ns][1] * s1;
                fin[ms][ns][2] += cur[ms][ns][2] * s0;
                fin[ms][ns][3] += cur[ms][ns][3] * s1;
                cur[ms][ns][0] = 0.f; cur[ms][ns][1] = 0.f;
                cur[ms][ns][2] = 0.f; cur[ms][ns][3] = 0.f;
            }
        }
    }

    const int hw0 = (p0 & 1023);
#pragma unroll
    for (int ms = 0; ms < 2; ms++)
#pragma unroll
        for (int ns = 0; ns < 4; ns++) {
            int row  = o_base + warp_m * 32 + ms * 16 + (lane >> 2);
            int coln = hw0 + warp_n * 32 + ns * 8 + (lane & 3) * 2;
            float* p1 = out + (((size_t)(n_img * O_TOT + row)) << 10) + coln;
            *(float2*)p1 = make_float2(fin[ms][ns][0], fin[ms][ns][1]);
            float* p2 = p1 + ((size_t)8 << 10);
            *(float2*)p2 = make_float2(fin[ms][ns][2], fin[ms][ns][3]);
        }
}

// ---------------- launch ----------------
extern "C" void kernel_launch(void* const* d_in, const int* in_sizes, int n_in,
                              void* d_out, int out_size) {
    const float* x      = (const float*)d_in[0];
    const float* conv_w = (const float*)d_in[1];
    const float* gamma  = (const float*)d_in[2];
    const float* beta   = (const float*)d_in[3];
    const float* weight = (const float*)d_in[4];
    float* out = (float*)d_out;

    cudaFuncSetAttribute(gemm_mma, cudaFuncAttributeMaxDynamicSharedMemorySize, SMEM_GEMM);
    cudaFuncSetAttribute(fused_conv, cudaFuncAttributeMaxDynamicSharedMemorySize, SMEM_CONV);

    fused_pre  <<<TX_BLOCKS + CA_BLOCKS, 256>>>(x, conv_w);
    fused_conv <<<CV_BLOCKS + PA_BLOCKS, 256, SMEM_CONV>>>(weight);
    reduce_bn  <<<9, 256>>>(gamma, beta);
    gemm_mma   <<<dim3(NPIX / N_TILE, O_TOT / M_TILE), 256, SMEM_GEMM>>>(out);
}

// round 17
// speedup vs baseline: 1.2658x; 1.0464x over previous
#include <cuda_runtime.h>
#include <cuda_fp16.h>
#include <cstdint>

// ---------------- problem constants ----------------
#define C_TOT   2048
#define L_TOT   9
#define K_TOT   (C_TOT * L_TOT)     // 18432
#define NPIX    4096
#define O_TOT   256

// ---------------- GEMM tiling ----------------
#define N_TILE   64
#define M_TILE   128
#define K_CHUNK  128
#define NCHUNK   (K_TOT / K_CHUNK)  // 144 = 9 l * 16

// ---------------- device scratch ----------------
__device__ __half g_a[O_TOT * K_TOT];           // A fp16, [o][l*2048+c]  9.4MB
__device__ __half g_xt[NPIX * C_TOT];           // fp16 x-transpose [p][c] 16.8MB
__device__ __half g_ca[16 * K_TOT];             // conv A fp16 [j(pad16)][l*2048+c]
__device__ float g_cpart[L_TOT * L_TOT * NPIX]; // conv partials [l][j][p] 1.3MB
__device__ float g_sigma[L_TOT * NPIX];
__device__ float g_scale[L_TOT];
__device__ float g_shift[L_TOT];

// ---------------- helpers ----------------
__device__ __forceinline__ uint32_t smem_u32(const void* p) {
    uint32_t a;
    asm("{ .reg .u64 t; cvta.to.shared.u64 t, %1; cvt.u32.u64 %0, t; }" : "=r"(a) : "l"(p));
    return a;
}
__device__ __forceinline__ void ldsm4(uint32_t* r, uint32_t addr) {
    asm volatile("ldmatrix.sync.aligned.m8n8.x4.shared.b16 {%0,%1,%2,%3}, [%4];"
        : "=r"(r[0]), "=r"(r[1]), "=r"(r[2]), "=r"(r[3]) : "r"(addr));
}
__device__ __forceinline__ void ldsm2(uint32_t* r, uint32_t addr) {
    asm volatile("ldmatrix.sync.aligned.m8n8.x2.shared.b16 {%0,%1}, [%2];"
        : "=r"(r[0]), "=r"(r[1]) : "r"(addr));
}
__device__ __forceinline__ void mma16816(float* d, const uint32_t* a, const uint32_t* b) {
    asm volatile(
        "mma.sync.aligned.m16n8k16.row.col.f32.f16.f16.f32 "
        "{%0,%1,%2,%3}, {%4,%5,%6,%7}, {%8,%9}, {%0,%1,%2,%3};"
        : "+f"(d[0]), "+f"(d[1]), "+f"(d[2]), "+f"(d[3])
        : "r"(a[0]), "r"(a[1]), "r"(a[2]), "r"(a[3]), "r"(b[0]), "r"(b[1]));
}
#define CP_ASYNC16(dst, src) \
    asm volatile("cp.async.cg.shared.global [%0], [%1], 16;" \
        :: "r"((uint32_t)(dst)), "l"(src) : "memory")
#define CP_ASYNC16Z(dst, src, ssz) \
    asm volatile("cp.async.cg.shared.global [%0], [%1], 16, %2;" \
        :: "r"((uint32_t)(dst)), "l"(src), "r"(ssz) : "memory")
#define CP_COMMIT()  asm volatile("cp.async.commit_group;" ::: "memory")
#define CP_WAIT0()   asm volatile("cp.async.wait_group 0;" ::: "memory")

// ---------------- shared GEMM SMEM layout ----------------
#define ROW_B     272u                      // 128 fp16 = 256B + 16B pad
#define A_TILE_B  (128u * ROW_B)            // 34816
#define B_TILE_B  (64u * ROW_B)             // 17408
#define BUF_B     (A_TILE_B + B_TILE_B)     // 52224
#define OFF_S     (2u * BUF_B)
#define SMEM_GEMM (OFF_S + 9u * 64u * 4u)   // 106752

// conv_mma smem
#define CA_TILE_B (16u * ROW_B)             // 4352
#define CBUF_B    (CA_TILE_B + B_TILE_B)    // 21760
#define SMEM_CONV (2u * CBUF_B)             // 43520

// grid split constants
#define TX_BLOCKS  ((NPIX / 64) * (C_TOT / 64))   // 2048
#define CA_BLOCKS  ((16 * K_TOT) / 256)           // 1152
#define CV_BLOCKS  ((NPIX / 64) * L_TOT)          // 576
#define PA_BLOCKS  ((O_TOT * C_TOT) / 256)        // 2048

// ================= fused pre: transpose_x + prep_ca =================
__global__ __launch_bounds__(256) void fused_pre(const float* __restrict__ x,
                                                 const float* __restrict__ cw) {
    const int bid = blockIdx.x;
    const int tid = threadIdx.x;
    if (bid < TX_BLOCKS) {
        __shared__ float t[64][65];
        const int p0 = (bid & 63) * 64;
        const int c0 = (bid >> 6) * 64;
        const int pc = tid & 63;
        const int cr = tid >> 6;
        const int p = p0 + pc;
        const int n = p >> 10, hw = p & 1023;
        const float* xp = x + (((size_t)(n * C_TOT + c0)) << 10) + hw;
#pragma unroll
        for (int it = 0; it < 16; it++) {
            int c = cr + it * 4;
            t[c][pc] = xp[(size_t)c << 10];
        }
        __syncthreads();
#pragma unroll
        for (int it = 0; it < 16; it++) {
            int prow = cr + it * 4;
            g_xt[(size_t)(p0 + prow) * C_TOT + c0 + pc] = __float2half_rn(t[pc][prow]);
        }
    } else {
        int i = (bid - TX_BLOCKS) * 256 + tid;
        int j = i / K_TOT, r = i - j * K_TOT;
        int l = r >> 11, c = r & 2047;
        __half v = __ushort_as_half((unsigned short)0);
        if (j < 9) v = __float2half_rn(cw[(size_t)j * K_TOT + c * 9 + l]);
        g_ca[i] = v;
    }
}

// ================= fused conv: conv_mma (first) + prep_a (filler) =================
__global__ __launch_bounds__(256, 1) void fused_conv(const float* __restrict__ w) {
    const int bid = blockIdx.x;
    const int tid = threadIdx.x;

    if (bid >= CV_BLOCKS) {
        int t = (bid - CV_BLOCKS) * 256 + tid;
        int o = t >> 11, c = t & 2047;
        const float* src = w + (size_t)o * K_TOT + c * 9;
#pragma unroll
        for (int l = 0; l < 9; l++)
            g_a[(size_t)o * K_TOT + l * C_TOT + c] = __float2half_rn(src[l]);
        return;
    }

    extern __shared__ char smem_raw[];
    const uint32_t base = smem_u32(smem_raw);

    const int lane = tid & 31;
    const int warp_n = tid >> 5;
    const int p0 = (bid & 63) * 64;
    const int l  = bid >> 6;
    const int dy = l / 3 - 1, dx = l % 3 - 1;

    const int aRowT = tid >> 4;
    const int aC16  = tid & 15;
    const __half* ag = g_ca + (size_t)aRowT * K_TOT + (size_t)l * C_TOT + aC16 * 8;
    const int bRowT = tid >> 2;
    const int bC16  = tid & 3;
    const int pb = p0 + bRowT;
    const int yb = (pb & 1023) >> 5, xb = pb & 31;
    const bool v = ((unsigned)(yb + dy) < 32u) & ((unsigned)(xb + dx) < 32u);
    const uint32_t ssz = v ? 16u : 0u;
    const __half* gb_base = v
        ? (g_xt + (size_t)pb * C_TOT + (ptrdiff_t)(dy * 32 + dx) * C_TOT + bC16 * 8)
        : g_xt;

    float acc[4] = {0.f, 0.f, 0.f, 0.f};

    auto CPA = [&](int ki, uint32_t buf) {
        uint32_t aB = base + buf * CBUF_B
                    + (uint32_t)aRowT * ROW_B + (uint32_t)aC16 * 16;
        CP_ASYNC16(aB, ag + (size_t)ki * K_CHUNK);
        const __half* gb = gb_base + (size_t)ki * K_CHUNK;
        uint32_t bB = base + buf * CBUF_B + CA_TILE_B
                    + (uint32_t)bRowT * ROW_B + (uint32_t)bC16 * 16;
#pragma unroll
        for (int it = 0; it < 4; it++)
            CP_ASYNC16Z(bB + (uint32_t)it * 64u, gb + (size_t)it * 32, ssz);
        CP_COMMIT();
    };

    auto COMPUTE = [&](uint32_t buf) {
        uint32_t aB = base + buf * CBUF_B;
        uint32_t bB = aB + CA_TILE_B;
        const uint32_t aAddr0 = aB + (uint32_t)(lane & 15) * ROW_B
                              + (uint32_t)(((lane >> 4) & 1) * 16);
        const uint32_t bAddr0 = bB + (uint32_t)(warp_n * 8 + (lane & 7)) * ROW_B
                              + (uint32_t)(((lane >> 3) & 1) * 16);
#pragma unroll
        for (int ks = 0; ks < 8; ks++) {
            uint32_t aF[4], bF[2];
            ldsm4(aF, aAddr0 + ks * 32);
            ldsm2(bF, bAddr0 + ks * 32);
            mma16816(acc, aF, bF);
        }
    };

    CPA(0, 0);
    CP_WAIT0();
    __syncthreads();

    for (int ki = 0; ki < 16; ki++) {
        const uint32_t buf = ki & 1;
        if (ki + 1 < 16) CPA(ki + 1, buf ^ 1);
        COMPUTE(buf);
        CP_WAIT0();
        __syncthreads();
    }

    int j0 = lane >> 2;
    int p  = p0 + warp_n * 8 + (lane & 3) * 2;
    float* cp = g_cpart + (size_t)l * (L_TOT * NPIX);
    if (j0 < 9) {
        cp[j0 * NPIX + p]     = acc[0];
        cp[j0 * NPIX + p + 1] = acc[1];
    }
    if (j0 == 0) {
        cp[8 * NPIX + p]     = acc[2];
        cp[8 * NPIX + p + 1] = acc[3];
    }
}

// ================= fused reduce + BN stats (grid 9) =================
__global__ __launch_bounds__(256) void reduce_bn(const float* __restrict__ gamma,
                                                 const float* __restrict__ beta) {
    __shared__ float shs[256], shq[256];
    const int j = blockIdx.x, tid = threadIdx.x;
    float s = 0.f, q = 0.f;
    for (int i = tid; i < NPIX; i += 256) {
        float v = 0.f;
#pragma unroll
        for (int l = 0; l < L_TOT; l++)
            v += g_cpart[(size_t)l * (L_TOT * NPIX) + j * NPIX + i];
        g_sigma[j * NPIX + i] = v;
        s += v; q += v * v;
    }
    shs[tid] = s; shq[tid] = q;
    __syncthreads();
    for (int st = 128; st > 0; st >>= 1) {
        if (tid < st) { shs[tid] += shs[tid + st]; shq[tid] += shq[tid + st]; }
        __syncthreads();
    }
    if (tid == 0) {
        float mean = shs[0] * (1.f / NPIX);
        float var  = shq[0] * (1.f / NPIX) - mean * mean;
        float inv  = rsqrtf(var + 1e-5f);
        float sc   = gamma[j] * inv;
        g_scale[j] = sc;
        g_shift[j] = beta[j] - mean * sc;
    }
}

// ================= main GEMM: 512 threads, 16 warps (8 m x 2 n), warp tile 16x32 =================
// out[o,p] = sum_l s_l[p] * sum_c A[o][l*2048+c] * xt[p + off_l][c]
__global__ __launch_bounds__(512, 1) void gemm_mma(float* __restrict__ out) {
    extern __shared__ char smem_raw[];
    const uint32_t base = smem_u32(smem_raw);
    float* s_sh = (float*)(smem_raw + OFF_S);

    const int tid  = threadIdx.x;
    const int lane = tid & 31;
    const int wid  = tid >> 5;
    const int warp_m = wid & 7;                 // 8 groups x 16 rows
    const int warp_n = wid >> 3;                // 2 groups x 32 px
    const int p0     = blockIdx.x * N_TILE;
    const int o_base = blockIdx.y * M_TILE;
    const int n_img  = p0 >> 10;

    // inline softmax for this pixel tile
    if (tid < 64) {
        const int pp = tid;
        float v[9];
        float m = -1e30f;
#pragma unroll
        for (int j = 0; j < 9; j++) {
            v[j] = g_sigma[j * NPIX + p0 + pp] * g_scale[j] + g_shift[j];
            m = fmaxf(m, v[j]);
        }
        float sum = 0.f;
#pragma unroll
        for (int j = 0; j < 9; j++) { v[j] = expf(v[j] - m); sum += v[j]; }
        float inv = 1.f / sum;
#pragma unroll
        for (int j = 0; j < 9; j++) s_sh[j * 64 + pp] = v[j] * inv;
    }
    __syncthreads();

    // cp.async geometry (512 threads)
    // A: 128 rows x 16 vec16 = 2048 vectors -> 4 per thread (rows aRowT + 32*it)
    const int aRowT = tid >> 4;                 // 0..31
    const int aC16  = tid & 15;                 // 0..15
    const __half* ag = g_a + (size_t)(o_base + aRowT) * K_TOT + aC16 * 8;
    // B: 64 rows x 16 vec16 = 1024 vectors -> threads 0..255, 4 each
    const int bRowT = (tid & 255) >> 2;
    const int bC16  = tid & 3;
    const int pb = p0 + bRowT;
    const int yb = (pb & 1023) >> 5, xb = pb & 31;
    const __half* xt_row = g_xt + (size_t)pb * C_TOT + bC16 * 8;
    const bool doB = tid < 256;

    const uint32_t aRow  = (uint32_t)(warp_m * 16 + (lane & 15));
    const uint32_t aColB = (uint32_t)(((lane >> 4) & 1) * 16);
    const uint32_t bRow  = (uint32_t)(warp_n * 32 + ((lane >> 4) & 1) * 8 + (lane & 7));
    const uint32_t bColB = (uint32_t)(((lane >> 3) & 1) * 16);

    float fin[4][4], cur[4][4];
#pragma unroll
    for (int b = 0; b < 4; b++)
#pragma unroll
        for (int c = 0; c < 4; c++) { fin[b][c] = 0.f; cur[b][c] = 0.f; }

    auto CPA = [&](int kt, uint32_t buf) {
        uint32_t aB = base + buf * BUF_B
                    + (uint32_t)aRowT * ROW_B + (uint32_t)aC16 * 16;
        const __half* ga = ag + (size_t)kt * K_CHUNK;
#pragma unroll
        for (int it = 0; it < 4; it++)
            CP_ASYNC16(aB + (uint32_t)it * 32u * ROW_B, ga + (size_t)it * 32 * K_TOT);
        if (doB) {
            int l  = kt >> 4;
            int dy = l / 3 - 1, dx = l - l / 3 * 3 - 1;
            bool v = ((unsigned)(yb + dy) < 32u) & ((unsigned)(xb + dx) < 32u);
            uint32_t ssz = v ? 16u : 0u;
            const __half* gb = v ? (xt_row + (ptrdiff_t)(dy * 32 + dx) * C_TOT) : g_xt;
            gb += (size_t)(kt & 15) * K_CHUNK;
            uint32_t bB = base + buf * BUF_B + A_TILE_B
                        + (uint32_t)bRowT * ROW_B + (uint32_t)bC16 * 16;
#pragma unroll
            for (int it = 0; it < 4; it++)
                CP_ASYNC16Z(bB + (uint32_t)it * 64u, gb + (size_t)it * 32, ssz);
        }
        CP_COMMIT();
    };

    auto COMPUTE = [&](uint32_t buf) {
        uint32_t aB = base + buf * BUF_B;
        uint32_t bB = aB + A_TILE_B;
#pragma unroll
        for (int ks = 0; ks < 8; ks++) {
            uint32_t aF[4], bF[2][4];
            ldsm4(aF, aB + aRow * ROW_B + aColB + ks * 32);
#pragma unroll
            for (int np = 0; np < 2; np++)
                ldsm4(bF[np], bB + (bRow + np * 16) * ROW_B + bColB + ks * 32);
#pragma unroll
            for (int ns = 0; ns < 4; ns++)
                mma16816(cur[ns], aF, &bF[ns >> 1][(ns & 1) * 2]);
        }
    };

    CPA(0, 0);
    CP_WAIT0();
    __syncthreads();

    for (int lt = 0; lt < 9; lt++) {
#pragma unroll 1
        for (int ki = 0; ki < 16; ki++) {
            const int kt = lt * 16 + ki;
            const uint32_t buf = kt & 1;
            if (kt + 1 < NCHUNK) CPA(kt + 1, buf ^ 1);
            COMPUTE(buf);
            CP_WAIT0();
            __syncthreads();
        }
#pragma unroll
        for (int ns = 0; ns < 4; ns++) {
            int cn = warp_n * 32 + ns * 8 + (lane & 3) * 2;
            float s0 = s_sh[lt * 64 + cn];
            float s1 = s_sh[lt * 64 + cn + 1];
            fin[ns][0] += cur[ns][0] * s0;
            fin[ns][1] += cur[ns][1] * s1;
            fin[ns][2] += cur[ns][2] * s0;
            fin[ns][3] += cur[ns][3] * s1;
            cur[ns][0] = 0.f; cur[ns][1] = 0.f;
            cur[ns][2] = 0.f; cur[ns][3] = 0.f;
        }
    }

    const int hw0 = (p0 & 1023);
#pragma unroll
    for (int ns = 0; ns < 4; ns++) {
        int row  = o_base + warp_m * 16 + (lane >> 2);
        int coln = hw0 + warp_n * 32 + ns * 8 + (lane & 3) * 2;
        float* p1 = out + (((size_t)(n_img * O_TOT + row)) << 10) + coln;
        *(float2*)p1 = make_float2(fin[ns][0], fin[ns][1]);
        float* p2 = p1 + ((size_t)8 << 10);
        *(float2*)p2 = make_float2(fin[ns][2], fin[ns][3]);
    }
}

// ---------------- launch ----------------
extern "C" void kernel_launch(void* const* d_in, const int* in_sizes, int n_in,
                              void* d_out, int out_size) {
    const float* x      = (const float*)d_in[0];
    const float* conv_w = (const float*)d_in[1];
    const float* gamma  = (const float*)d_in[2];
    const float* beta   = (const float*)d_in[3];
    const float* weight = (const float*)d_in[4];
    float* out = (float*)d_out;

    cudaFuncSetAttribute(gemm_mma, cudaFuncAttributeMaxDynamicSharedMemorySize, SMEM_GEMM);
    cudaFuncSetAttribute(fused_conv, cudaFuncAttributeMaxDynamicSharedMemorySize, SMEM_CONV);

    fused_pre  <<<TX_BLOCKS + CA_BLOCKS, 256>>>(x, conv_w);
    fused_conv <<<CV_BLOCKS + PA_BLOCKS, 256, SMEM_CONV>>>(weight);
    reduce_bn  <<<9, 256>>>(gamma, beta);
    gemm_mma   <<<dim3(NPIX / N_TILE, O_TOT / M_TILE), 512, SMEM_GEMM>>>(out);
}